// round 15
// baseline (speedup 1.0000x reference)
#include <cuda_runtime.h>
#include <cuda_fp16.h>
#include <cstdint>
#include <cstddef>

constexpr int B  = 65536;
constexpr int T  = 30;
constexpr int MT = 128;          // samples per CTA
constexpr int THREADS = 512;     // 16 warps: 2 (m) x 8 (n), warp tile 64x32

// ---------------- Fused-kernel smem offsets (bytes) ----------------
constexpr int SM_X0    = 0;       // x ping [128][48B] K=16 (cols0-8, rest 0)
constexpr int SM_X1    = 6144;    // x pong
constexpr int SM_WIH0  = 12288;   // [256 n][48B] Wih0 fp16 (cols0-8, rest 0)
constexpr int SM_BIAS0 = 24576;   // 256 f32, reordered gate cols (layer0)
constexpr int SM_BIAS1 = 25600;   // 256 f32 (layer1)
constexpr int SM_H0A   = 26624;   // h0 buffer A [128][128B] swz fp16
constexpr int SM_H0B   = 43008;   // h0 buffer B
constexpr int SM_H1A   = 59392;   // h1 buffer A
constexpr int SM_H1B   = 75776;   // h1 buffer B
constexpr int SM_WHH0  = 92160;   // [256][128B] swz fp16
constexpr int SM_W1IH  = 124928;
constexpr int SM_W1HH  = 157696;
constexpr int SM_LN    = 190464;  // [128][68] f32 final h1 for LayerNorm
constexpr int SM_TOTAL = 190464 + 128 * 68 * 4;   // 225280

// ---------------- helpers ----------------
__device__ __forceinline__ uint32_t smem_u32(const void* p) {
    uint32_t a;
    asm("{ .reg .u64 t; cvta.to.shared.u64 t, %1; cvt.u32.u64 %0, t; }"
        : "=r"(a) : "l"(p));
    return a;
}
// hardware tanh (sm_75+): 1 MUFU op, ~2^-11 accuracy
__device__ __forceinline__ float tanha(float x) {
    float r;
    asm("tanh.approx.f32 %0, %1;" : "=f"(r) : "f"(x));
    return r;
}
__device__ __forceinline__ float sigf(float x) {
    return fmaf(tanha(0.5f * x), 0.5f, 0.5f);
}
__device__ __forceinline__ uint32_t f2h2(float a, float b) {
    __half2 h = __floats2half2_rn(a, b);
    return *reinterpret_cast<uint32_t*>(&h);
}

__device__ __forceinline__ void ldsm4(uint32_t (&r)[4], uint32_t addr) {
    asm volatile("ldmatrix.sync.aligned.m8n8.x4.shared.b16 {%0,%1,%2,%3}, [%4];"
        : "=r"(r[0]), "=r"(r[1]), "=r"(r[2]), "=r"(r[3]) : "r"(addr));
}
__device__ __forceinline__ void mma_f16(float (&d)[4], const uint32_t (&a)[4],
                                        uint32_t b0, uint32_t b1) {
    asm volatile(
        "mma.sync.aligned.m16n8k16.row.col.f32.f16.f16.f32 "
        "{%0,%1,%2,%3},{%4,%5,%6,%7},{%8,%9},{%0,%1,%2,%3};"
        : "+f"(d[0]), "+f"(d[1]), "+f"(d[2]), "+f"(d[3])
        : "r"(a[0]), "r"(a[1]), "r"(a[2]), "r"(a[3]), "r"(b0), "r"(b1));
}

// Warp GEMM: A tile (MI*16 rows) x one B tile (32 n-cols), acc[MI][4][4].
// KS k16-steps; strides in bytes; SW = XOR-16B-chunk swizzle for 128B-stride tiles.
template<int KS, int SA, int SB, bool SWA, bool SWB, int MI>
__device__ __forceinline__ void gemm_acc(uint32_t aBase, uint32_t bBase,
                                         float (&acc)[MI][4][4],
                                         int mrow0, int ncol0, int lane)
{
    const int grp = lane >> 3, j = lane & 7;
    const int arow_off = ((grp & 1) << 3) + j;
    const int ach_off  = grp >> 1;
    const int brow_off = ((grp >> 1) << 3) + j;
    const int bch_off  = grp & 1;
#pragma unroll
    for (int kk = 0; kk < KS; kk++) {
        uint32_t a[MI][4];
#pragma unroll
        for (int mi = 0; mi < MI; mi++) {
            int row = mrow0 + mi * 16 + arow_off;
            int ch  = 2 * kk + ach_off;
            uint32_t ad = aBase + row * SA + ((SWA ? (ch ^ (row & 7)) : ch) << 4);
            ldsm4(a[mi], ad);
        }
#pragma unroll
        for (int ni = 0; ni < 2; ni++) {
            int row = ncol0 + ni * 16 + brow_off;
            int ch  = 2 * kk + bch_off;
            uint32_t bd = bBase + row * SB + ((SWB ? (ch ^ (row & 7)) : ch) << 4);
            uint32_t bf[4];
            ldsm4(bf, bd);
#pragma unroll
            for (int mi = 0; mi < MI; mi++) {
                mma_f16(acc[mi][2 * ni],     a[mi], bf[0], bf[1]);
                mma_f16(acc[mi][2 * ni + 1], a[mi], bf[2], bf[3]);
            }
        }
    }
}

// Gate epilogue: acc (pre-activations, cols = unit*4+type) + fp32 bias ->
// cell update -> h written fp16 into DESTINATION ping-pong tile (disjoint from
// GEMM sources, so no barrier before it), or fp32 into LN buffer on last step.
template<bool LNOUT, int MI>
__device__ __forceinline__ void epilogue(float (&acc)[MI][4][4], float (&cs)[MI][4],
                                         char* sm, int hhOff, const float* bias,
                                         int lnOff, int mrow0, int ncol0, int lane)
{
    const int  odd   = lane & 1;
    const int  rb    = mrow0 + (lane >> 2) + (odd ? 8 : 0);
    const int  ub    = (ncol0 >> 2) + ((lane & 3) >> 1);
#pragma unroll
    for (int mi = 0; mi < MI; mi++) {
#pragma unroll
        for (int nj = 0; nj < 4; nj++) {
            int n0 = ncol0 + nj * 8 + 2 * (lane & 3);
            float b0 = bias[n0], b1 = bias[n0 + 1];
            float c0 = acc[mi][nj][0] + b0, c1 = acc[mi][nj][1] + b1;
            float c2 = acc[mi][nj][2] + b0, c3 = acc[mi][nj][3] + b1;
            // even lanes hold (i,f) cols; odd lanes hold (g,o) cols; rows {r, r+8}
            float A0, A1, A2, A3;
            if (!odd) { A0 = sigf(c0);  A1 = sigf(c1); A2 = sigf(c2);  A3 = sigf(c3); }
            else      { A0 = tanha(c0); A1 = sigf(c1); A2 = tanha(c2); A3 = sigf(c3); }
            // exchange: even keeps row r (needs g,o from odd); odd keeps row r+8 (needs i,f)
            float v0 = odd ? A0 : A2;
            float v1 = odd ? A1 : A3;
            float r0 = __shfl_xor_sync(0xffffffffu, v0, 1);
            float r1 = __shfl_xor_sync(0xffffffffu, v1, 1);
            float iv = odd ? r0 : A0;
            float fv = odd ? r1 : A1;
            float gv = odd ? A2 : r0;
            float ov = odd ? A3 : r1;
            float cc = fv * cs[mi][nj] + iv * gv;
            cs[mi][nj] = cc;
            float hv = ov * tanha(cc);
            int row = rb + mi * 16;
            int u   = ub + 2 * nj;
            if (LNOUT) {
                ((float*)(sm + lnOff))[row * 68 + u] = hv;
            } else {
                __half hh = __float2half_rn(hv);
                int ch = u >> 3;
                int ba = row * 128 + ((ch ^ (row & 7)) << 4) + ((2 * u) & 15);
                *(__half*)(sm + hhOff + ba) = hh;
            }
        }
    }
}

// =====================================================================
// Fused kernel: x -> layer0 LSTM -> layer1 LSTM (pipelined) -> LayerNorm
// Iteration i computes layer0 step i and layer1 step i-1 (independent).
// =====================================================================
__global__ void __launch_bounds__(THREADS, 1) k_fused(
    const float* __restrict__ x,
    const float* __restrict__ Wih0, const float* __restrict__ Whh0,
    const float* __restrict__ bih0, const float* __restrict__ bhh0,
    const float* __restrict__ Wih1, const float* __restrict__ Whh1,
    const float* __restrict__ bih1, const float* __restrict__ bhh1,
    const float* __restrict__ gamma, const float* __restrict__ beta,
    float* __restrict__ out)
{
    extern __shared__ __align__(1024) char sm[];
    const uint32_t sb = smem_u32(sm);
    const int tid = threadIdx.x, wid = tid >> 5, lane = tid & 31;
    const int mrow0 = (wid & 1) * 64;
    const int ncol0 = (wid >> 1) * 32;
    const int blk = blockIdx.x;

    // prefetch x_0 early (overlaps staging)
    float xv[9];
    if (tid < MT) {
        const float* xr = x + ((size_t)(blk * MT + tid) * T + 0) * 9;
#pragma unroll
        for (int i = 0; i < 9; i++) xv[i] = xr[i];
    }

    // zero X0/X1/WIH0 region and all four h tiles
    for (int i = tid; i < 24576 / 16; i += THREADS)
        ((uint4*)(sm + SM_X0))[i] = make_uint4(0, 0, 0, 0);
    for (int i = tid; i < 65536 / 16; i += THREADS)
        ((uint4*)(sm + SM_H0A))[i] = make_uint4(0, 0, 0, 0);
    __syncthreads();

    // Wih0 fp16 [256 n][48B]: cols 0-8 weights, rest zero
    for (int idx = tid; idx < 256 * 9; idx += THREADS) {
        int g = idx / 9, i2 = idx - g * 9;
        int n = (g & 63) * 4 + (g >> 6);
        *(__half*)(sm + SM_WIH0 + n * 48 + 2 * i2) = __float2half_rn(Wih0[idx]);
    }
    // bias tables (reordered gate cols)
    for (int g = tid; g < 256; g += THREADS) {
        int n = (g & 63) * 4 + (g >> 6);
        ((float*)(sm + SM_BIAS0))[n] = bih0[g] + bhh0[g];
        ((float*)(sm + SM_BIAS1))[n] = bih1[g] + bhh1[g];
    }
    // swizzled fp16 weight tiles: Whh0, Wih1, Whh1
    for (int idx = tid; idx < 256 * 64; idx += THREADS) {
        int g = idx >> 6, k = idx & 63;
        int n = (g & 63) * 4 + (g >> 6);
        int ba = n * 128 + (((k >> 3) ^ (n & 7)) << 4) + ((2 * k) & 15);
        *(__half*)(sm + SM_WHH0 + ba) = __float2half_rn(Whh0[idx]);
        *(__half*)(sm + SM_W1IH + ba) = __float2half_rn(Wih1[idx]);
        *(__half*)(sm + SM_W1HH + ba) = __float2half_rn(Whh1[idx]);
    }
    // stage x_0 into X0
    if (tid < MT) {
        char* rp = sm + SM_X0 + tid * 48;
        ((uint4*)rp)[0] = make_uint4(f2h2(xv[0], xv[1]), f2h2(xv[2], xv[3]),
                                     f2h2(xv[4], xv[5]), f2h2(xv[6], xv[7]));
        ((uint4*)rp)[1] = make_uint4(f2h2(xv[8], 0.f), 0, 0, 0);
    }
    __syncthreads();

    float cs0[4][4], cs1[4][4];
#pragma unroll
    for (int a = 0; a < 4; a++)
#pragma unroll
        for (int b = 0; b < 4; b++) { cs0[a][b] = 0.f; cs1[a][b] = 0.f; }

    // ---------- peeled iteration 0: layer0 step 0 only (h0 = 0 -> skip H-GEMM)
    {
        if (tid < MT) {
            const float* xr = x + ((size_t)(blk * MT + tid) * T + 1) * 9;
#pragma unroll
            for (int i = 0; i < 9; i++) xv[i] = xr[i];
        }
        float acc[4][4][4];
#pragma unroll
        for (int a = 0; a < 4; a++)
#pragma unroll
            for (int b = 0; b < 4; b++)
#pragma unroll
                for (int q = 0; q < 4; q++) acc[a][b][q] = 0.f;
        gemm_acc<1, 48, 48, false, false, 4>(sb + SM_X0, sb + SM_WIH0,
                                             acc, mrow0, ncol0, lane);
        // stage x_1 into X1 (disjoint from X0)
        if (tid < MT) {
            char* rp = sm + SM_X1 + tid * 48;
            ((uint4*)rp)[0] = make_uint4(f2h2(xv[0], xv[1]), f2h2(xv[2], xv[3]),
                                         f2h2(xv[4], xv[5]), f2h2(xv[6], xv[7]));
            ((uint4*)rp)[1] = make_uint4(f2h2(xv[8], 0.f), 0, 0, 0);
        }
        epilogue<false, 4>(acc, cs0, sm, SM_H0B, (const float*)(sm + SM_BIAS0),
                           0, mrow0, ncol0, lane);
        __syncthreads();
    }

    // ---------- main loop: iteration i = layer0 step i + layer1 step i-1
    for (int i = 1; i <= T; i++) {
        const int rd  = i & 1;
        const int h0rd = rd ? SM_H0B : SM_H0A;
        const int h0wr = rd ? SM_H0A : SM_H0B;
        const int h1rd = rd ? SM_H1B : SM_H1A;
        const int h1wr = rd ? SM_H1A : SM_H1B;
        const int xrd  = rd ? SM_X1 : SM_X0;
        const int xwr  = rd ? SM_X0 : SM_X1;

        // prefetch x_{i+1} (LDG at top; lands before staging below)
        if (i + 1 < T && tid < MT) {
            const float* xr = x + ((size_t)(blk * MT + tid) * T + (i + 1)) * 9;
#pragma unroll
            for (int q = 0; q < 9; q++) xv[q] = xr[q];
        }

        float acc[4][4][4];

        // ---- layer0 step i (skip on final iteration i == T)
        if (i < T) {
#pragma unroll
            for (int a = 0; a < 4; a++)
#pragma unroll
                for (int b = 0; b < 4; b++)
#pragma unroll
                    for (int q = 0; q < 4; q++) acc[a][b][q] = 0.f;
            gemm_acc<4, 128, 128, true, true, 4>(sb + h0rd, sb + SM_WHH0,
                                                 acc, mrow0, ncol0, lane);
            gemm_acc<1, 48, 48, false, false, 4>(sb + xrd, sb + SM_WIH0,
                                                 acc, mrow0, ncol0, lane);
            epilogue<false, 4>(acc, cs0, sm, h0wr, (const float*)(sm + SM_BIAS0),
                               0, mrow0, ncol0, lane);
        }

        // ---- layer1 step i-1 (input = h0_{i-1}, sitting in h0rd)
#pragma unroll
        for (int a = 0; a < 4; a++)
#pragma unroll
            for (int b = 0; b < 4; b++)
#pragma unroll
                for (int q = 0; q < 4; q++) acc[a][b][q] = 0.f;
        gemm_acc<4, 128, 128, true, true, 4>(sb + h0rd, sb + SM_W1IH,
                                             acc, mrow0, ncol0, lane);
        gemm_acc<4, 128, 128, true, true, 4>(sb + h1rd, sb + SM_W1HH,
                                             acc, mrow0, ncol0, lane);

        // stage x_{i+1} into pong (disjoint from xrd) — no barrier needed
        if (i + 1 < T && tid < MT) {
            char* rp = sm + xwr + tid * 48;
            ((uint4*)rp)[0] = make_uint4(f2h2(xv[0], xv[1]), f2h2(xv[2], xv[3]),
                                         f2h2(xv[4], xv[5]), f2h2(xv[6], xv[7]));
            ((uint4*)rp)[1] = make_uint4(f2h2(xv[8], 0.f), 0, 0, 0);
        }

        if (i < T) {
            epilogue<false, 4>(acc, cs1, sm, h1wr, (const float*)(sm + SM_BIAS1),
                               0, mrow0, ncol0, lane);
        } else {
            // final layer1 step: write fp32 h into LN buffer
            epilogue<true, 4>(acc, cs1, sm, 0, (const float*)(sm + SM_BIAS1),
                              SM_LN, mrow0, ncol0, lane);
        }
        __syncthreads();   // single barrier per iteration
    }

    // LayerNorm over final h1 (fp32 buffer), one thread per sample
    if (tid < MT) {
        const float* row = (const float*)(sm + SM_LN) + tid * 68;
        float s = 0.f;
#pragma unroll
        for (int k = 0; k < 64; k++) s += row[k];
        float mean = s * (1.f / 64.f);
        float vs = 0.f;
#pragma unroll
        for (int k = 0; k < 64; k++) { float d = row[k] - mean; vs += d * d; }
        float rstd = rsqrtf(vs * (1.f / 64.f) + 1e-5f);
        float4* op = (float4*)(out + (size_t)(blk * MT + tid) * 64);
#pragma unroll
        for (int k = 0; k < 64; k += 4) {
            float4 o;
            o.x = (row[k + 0] - mean) * rstd * gamma[k + 0] + beta[k + 0];
            o.y = (row[k + 1] - mean) * rstd * gamma[k + 1] + beta[k + 1];
            o.z = (row[k + 2] - mean) * rstd * gamma[k + 2] + beta[k + 2];
            o.w = (row[k + 3] - mean) * rstd * gamma[k + 3] + beta[k + 3];
            op[k >> 2] = o;
        }
    }
}

// =====================================================================
extern "C" void kernel_launch(void* const* d_in, const int* in_sizes, int n_in,
                              void* d_out, int out_size) {
    (void)in_sizes; (void)n_in; (void)out_size;
    const float* x     = (const float*)d_in[0];
    const float* Wih0  = (const float*)d_in[1];
    const float* Whh0  = (const float*)d_in[2];
    const float* bih0  = (const float*)d_in[3];
    const float* bhh0  = (const float*)d_in[4];
    const float* Wih1  = (const float*)d_in[5];
    const float* Whh1  = (const float*)d_in[6];
    const float* bih1  = (const float*)d_in[7];
    const float* bhh1  = (const float*)d_in[8];
    const float* gamma = (const float*)d_in[9];
    const float* beta  = (const float*)d_in[10];
    float* out = (float*)d_out;

    cudaFuncSetAttribute(k_fused, cudaFuncAttributeMaxDynamicSharedMemorySize,
                         SM_TOTAL);
    k_fused<<<B / MT, THREADS, SM_TOTAL>>>(x, Wih0, Whh0, bih0, bhh0,
                                           Wih1, Whh1, bih1, bhh1,
                                           gamma, beta, out);
}

// round 16
// speedup vs baseline: 1.1674x; 1.1674x over previous
#include <cuda_runtime.h>
#include <cuda_fp16.h>
#include <cstdint>
#include <cstddef>

constexpr int B  = 65536;
constexpr int T  = 30;
constexpr int MT = 128;          // samples per CTA
constexpr int THREADS = 512;     // 16 warps: 2 (m) x 8 (n), warp tile 64x32

// ---------------- Kernel0 smem offsets (bytes) ----------------
constexpr int SM0_X0    = 0;       // x ping [128][48B] K=16 (cols0-8, rest 0)
constexpr int SM0_X1    = 6144;    // x pong
constexpr int SM0_WIH   = 12288;   // [256 n][48B] Wih fp16 (cols0-8, rest 0)
constexpr int SM0_BIAS  = 24576;   // 256 f32, reordered gate cols
constexpr int SM0_HH0   = 25600;   // h0 fp16 ping [128][128B] swz
constexpr int SM0_HH1   = 41984;   // h0 fp16 pong
constexpr int SM0_WHH   = 58368;   // [256][128B] swz
constexpr int SM0_TOTAL = 91136;

// ---------------- Kernel1 smem offsets ----------------
constexpr int SM1_X0    = 0;       // staged h0 ping [128][128B] swz
constexpr int SM1_X1    = 16384;   // staged h0 pong
constexpr int SM1_H1H0  = 32768;   // h1 fp16 ping
constexpr int SM1_H1H1  = 49152;   // h1 fp16 pong
constexpr int SM1_WIH   = 65536;   // [256][128B] swz
constexpr int SM1_WHH   = 98304;
constexpr int SM1_BIAS  = 131072;  // 256 f32, reordered gate cols
constexpr int SM1_LN    = 132096;  // [128][68] f32 final h for LayerNorm
constexpr int SM1_TOTAL = 132096 + 128 * 68 * 4;   // 166912

// scratch: layer0 h fp16, [t][sample][8 x 16B chunks], coalesced both ways
__device__ uint4 g_h0[(size_t)T * B * 8];

// ---------------- helpers ----------------
__device__ __forceinline__ uint32_t smem_u32(const void* p) {
    uint32_t a;
    asm("{ .reg .u64 t; cvta.to.shared.u64 t, %1; cvt.u32.u64 %0, t; }"
        : "=r"(a) : "l"(p));
    return a;
}
// hardware tanh (sm_75+): 1 MUFU op
__device__ __forceinline__ float tanha(float x) {
    float r;
    asm("tanh.approx.f32 %0, %1;" : "=f"(r) : "f"(x));
    return r;
}
// packed fp16x2 hardware tanh: 1 MUFU op for two values
__device__ __forceinline__ uint32_t tanh2(uint32_t x2) {
    uint32_t r;
    asm("tanh.approx.f16x2 %0, %1;" : "=r"(r) : "r"(x2));
    return r;
}
__device__ __forceinline__ uint32_t f2h2(float a, float b) {
    __half2 h = __floats2half2_rn(a, b);
    return *reinterpret_cast<uint32_t*>(&h);
}
__device__ __forceinline__ float2 h22f2(uint32_t p) {
    return __half22float2(*reinterpret_cast<__half2*>(&p));
}

__device__ __forceinline__ void ldsm4(uint32_t (&r)[4], uint32_t addr) {
    asm volatile("ldmatrix.sync.aligned.m8n8.x4.shared.b16 {%0,%1,%2,%3}, [%4];"
        : "=r"(r[0]), "=r"(r[1]), "=r"(r[2]), "=r"(r[3]) : "r"(addr));
}
__device__ __forceinline__ void mma_f16(float (&d)[4], const uint32_t (&a)[4],
                                        uint32_t b0, uint32_t b1) {
    asm volatile(
        "mma.sync.aligned.m16n8k16.row.col.f32.f16.f16.f32 "
        "{%0,%1,%2,%3},{%4,%5,%6,%7},{%8,%9},{%0,%1,%2,%3};"
        : "+f"(d[0]), "+f"(d[1]), "+f"(d[2]), "+f"(d[3])
        : "r"(a[0]), "r"(a[1]), "r"(a[2]), "r"(a[3]), "r"(b0), "r"(b1));
}

// Warp GEMM: A tile (MI*16 rows) x one B tile (32 n-cols), acc[MI][4][4].
// KS k16-steps; strides in bytes; SW = XOR-16B-chunk swizzle for 128B-stride tiles.
template<int KS, int SA, int SB, bool SWA, bool SWB, int MI>
__device__ __forceinline__ void gemm_acc(uint32_t aBase, uint32_t bBase,
                                         float (&acc)[MI][4][4],
                                         int mrow0, int ncol0, int lane)
{
    const int grp = lane >> 3, j = lane & 7;
    const int arow_off = ((grp & 1) << 3) + j;
    const int ach_off  = grp >> 1;
    const int brow_off = ((grp >> 1) << 3) + j;
    const int bch_off  = grp & 1;
#pragma unroll
    for (int kk = 0; kk < KS; kk++) {
        uint32_t a[MI][4];
#pragma unroll
        for (int mi = 0; mi < MI; mi++) {
            int row = mrow0 + mi * 16 + arow_off;
            int ch  = 2 * kk + ach_off;
            uint32_t ad = aBase + row * SA + ((SWA ? (ch ^ (row & 7)) : ch) << 4);
            ldsm4(a[mi], ad);
        }
#pragma unroll
        for (int ni = 0; ni < 2; ni++) {
            int row = ncol0 + ni * 16 + brow_off;
            int ch  = 2 * kk + bch_off;
            uint32_t bd = bBase + row * SB + ((SWB ? (ch ^ (row & 7)) : ch) << 4);
            uint32_t bf[4];
            ldsm4(bf, bd);
#pragma unroll
            for (int mi = 0; mi < MI; mi++) {
                mma_f16(acc[mi][2 * ni],     a[mi], bf[0], bf[1]);
                mma_f16(acc[mi][2 * ni + 1], a[mi], bf[2], bf[3]);
            }
        }
    }
}

// Gate epilogue with PACKED f16x2 tanh gates:
//   even lanes hold (i,f) cols -> both sigmoids: tanh2(0.5c)*0.5+0.5
//   odd  lanes hold (g,o) cols -> (tanh, sigmoid): tanh2((c0, 0.5c1))
// One half2 shfl exchanges the pair. cc-tanh stays fp32 MUFU for cell precision.
template<bool LNOUT, int MI>
__device__ __forceinline__ void epilogue(float (&acc)[MI][4][4], float (&cs)[MI][4],
                                         char* sm, int hhOff, const float* bias,
                                         int lnOff, int mrow0, int ncol0, int lane)
{
    const int   odd = lane & 1;
    const int   rb  = mrow0 + (lane >> 2) + (odd ? 8 : 0);
    const int   ub  = (ncol0 >> 2) + ((lane & 3) >> 1);
    const float s0  = odd ? 1.0f : 0.5f;   // pre-scale, slots 0/2
    const float k0  = odd ? 1.0f : 0.5f;   // post-scale, slots 0/2
    const float a0  = odd ? 0.0f : 0.5f;   // post-offset, slots 0/2
#pragma unroll
    for (int mi = 0; mi < MI; mi++) {
#pragma unroll
        for (int nj = 0; nj < 4; nj++) {
            int n0 = ncol0 + nj * 8 + 2 * (lane & 3);
            float b0 = bias[n0], b1 = bias[n0 + 1];
            float c0 = acc[mi][nj][0] + b0, c1 = acc[mi][nj][1] + b1;
            float c2 = acc[mi][nj][2] + b0, c3 = acc[mi][nj][3] + b1;
            // packed gate activations: 2 MUFU for 4 gates
            uint32_t t01 = tanh2(f2h2(c0 * s0, c1 * 0.5f));
            uint32_t t23 = tanh2(f2h2(c2 * s0, c3 * 0.5f));
            float2 g01 = h22f2(t01), g23 = h22f2(t23);
            float A0 = fmaf(g01.x, k0, a0);
            float A1 = fmaf(g01.y, 0.5f, 0.5f);
            float A2 = fmaf(g23.x, k0, a0);
            float A3 = fmaf(g23.y, 0.5f, 0.5f);
            // exchange: even keeps row r (needs g,o from odd); odd keeps r+8 (needs i,f)
            float v0 = odd ? A0 : A2;
            float v1 = odd ? A1 : A3;
            uint32_t pv = f2h2(v0, v1);
            uint32_t pr = __shfl_xor_sync(0xffffffffu, pv, 1);
            float2 rr = h22f2(pr);
            float iv = odd ? rr.x : A0;
            float fv = odd ? rr.y : A1;
            float gv = odd ? A2 : rr.x;
            float ov = odd ? A3 : rr.y;
            float cc = fmaf(fv, cs[mi][nj], iv * gv);
            cs[mi][nj] = cc;
            float hv = ov * tanha(cc);
            int row = rb + mi * 16;
            int u   = ub + 2 * nj;
            if (LNOUT) {
                ((float*)(sm + lnOff))[row * 68 + u] = hv;
            } else {
                __half hh = __float2half_rn(hv);
                int ch = u >> 3;
                int ba = row * 128 + ((ch ^ (row & 7)) << 4) + ((2 * u) & 15);
                *(__half*)(sm + hhOff + ba) = hh;
            }
        }
    }
}

// =====================================================================
// Kernel 0: x -> h0 (fp16) -> global scratch
// =====================================================================
__global__ void __launch_bounds__(THREADS, 1) k_layer0(
    const float* __restrict__ x,
    const float* __restrict__ Wih, const float* __restrict__ Whh,
    const float* __restrict__ bih, const float* __restrict__ bhh)
{
    extern __shared__ __align__(1024) char sm[];
    const uint32_t sb = smem_u32(sm);
    const int tid = threadIdx.x, wid = tid >> 5, lane = tid & 31;
    const int mrow0 = (wid & 1) * 64;
    const int ncol0 = (wid >> 1) * 32;
    const int blk = blockIdx.x;

    // prefetch x_0 early (overlaps weight staging)
    float xv[9];
    if (tid < MT) {
        const float* xr = x + ((size_t)(blk * MT + tid) * T + 0) * 9;
#pragma unroll
        for (int i = 0; i < 9; i++) xv[i] = xr[i];
    }

    // zero h ping-pong + X/WIH regions
    for (int i = tid; i < 32768 / 16; i += THREADS)
        ((uint4*)(sm + SM0_HH0))[i] = make_uint4(0, 0, 0, 0);
    for (int i = tid; i < 24576 / 16; i += THREADS)
        ((uint4*)(sm + SM0_X0))[i] = make_uint4(0, 0, 0, 0);
    __syncthreads();

    // Wih0 fp16 [256 n][48B]: cols 0-8 weights, rest zero; bias fp32 table
    for (int idx = tid; idx < 256 * 9; idx += THREADS) {
        int g = idx / 9, i2 = idx - g * 9;
        int n = (g & 63) * 4 + (g >> 6);
        *(__half*)(sm + SM0_WIH + n * 48 + 2 * i2) = __float2half_rn(Wih[idx]);
    }
    for (int g = tid; g < 256; g += THREADS) {
        int n = (g & 63) * 4 + (g >> 6);
        ((float*)(sm + SM0_BIAS))[n] = bih[g] + bhh[g];
    }
    // Whh0 fp16 tile (swizzled)
    for (int idx = tid; idx < 256 * 64; idx += THREADS) {
        int g = idx >> 6, k = idx & 63;
        int n = (g & 63) * 4 + (g >> 6);
        int ba = n * 128 + (((k >> 3) ^ (n & 7)) << 4) + ((2 * k) & 15);
        *(__half*)(sm + SM0_WHH + ba) = __float2half_rn(Whh[idx]);
    }
    // stage x_0 into X0
    if (tid < MT) {
        char* rp = sm + SM0_X0 + tid * 48;
        ((uint4*)rp)[0] = make_uint4(f2h2(xv[0], xv[1]), f2h2(xv[2], xv[3]),
                                     f2h2(xv[4], xv[5]), f2h2(xv[6], xv[7]));
        ((uint4*)rp)[1] = make_uint4(f2h2(xv[8], 0.f), 0, 0, 0);
    }
    __syncthreads();

    float cs[4][4];
#pragma unroll
    for (int a = 0; a < 4; a++)
#pragma unroll
        for (int b = 0; b < 4; b++) cs[a][b] = 0.f;

    for (int t = 0; t < T; t++) {
        const int rdH = (t & 1) ? SM0_HH1 : SM0_HH0;
        const int wrH = (t & 1) ? SM0_HH0 : SM0_HH1;
        const int rdX = (t & 1) ? SM0_X1 : SM0_X0;
        const int wrX = (t & 1) ? SM0_X0 : SM0_X1;

        // prefetch x_{t+1} (LDG issued at top; lands before staging below)
        if (t + 1 < T && tid < MT) {
            const float* xr = x + ((size_t)(blk * MT + tid) * T + (t + 1)) * 9;
#pragma unroll
            for (int i = 0; i < 9; i++) xv[i] = xr[i];
        }

        // store h_{t-1} -> global scratch (reads rdH: read/read vs H-GEMM)
        if (t > 0) {
            for (int i = tid; i < 1024; i += THREADS) {
                int row = i >> 3, ch = i & 7;
                uint32_t sa = row * 128 + ((ch ^ (row & 7)) << 4);
                size_t gi = ((size_t)(t - 1) * B + (size_t)blk * MT + row) * 8 + ch;
                g_h0[gi] = *(uint4*)(sm + rdH + sa);
            }
        }

        float acc[4][4][4];
#pragma unroll
        for (int a = 0; a < 4; a++)
#pragma unroll
            for (int b = 0; b < 4; b++)
#pragma unroll
                for (int q = 0; q < 4; q++) acc[a][b][q] = 0.f;

        gemm_acc<4, 128, 128, true, true, 4>(sb + rdH, sb + SM0_WHH,
                                             acc, mrow0, ncol0, lane);
        gemm_acc<1, 48, 48, false, false, 4>(sb + rdX, sb + SM0_WIH,
                                             acc, mrow0, ncol0, lane);

        // stage x_{t+1} into pong (disjoint from rdX) — no barrier needed
        if (t + 1 < T && tid < MT) {
            char* rp = sm + wrX + tid * 48;
            ((uint4*)rp)[0] = make_uint4(f2h2(xv[0], xv[1]), f2h2(xv[2], xv[3]),
                                         f2h2(xv[4], xv[5]), f2h2(xv[6], xv[7]));
            ((uint4*)rp)[1] = make_uint4(f2h2(xv[8], 0.f), 0, 0, 0);
        }

        // epilogue writes wrH (disjoint from rdH/rdX) — no barrier before it
        epilogue<false, 4>(acc, cs, sm, wrH, (const float*)(sm + SM0_BIAS),
                           0, mrow0, ncol0, lane);
        __syncthreads();   // single barrier per timestep
    }

    // store final h_{T-1} (lives in buf[T&1] = buf0)
    {
        const int rdH = (T & 1) ? SM0_HH1 : SM0_HH0;
        for (int i = tid; i < 1024; i += THREADS) {
            int row = i >> 3, ch = i & 7;
            uint32_t sa = row * 128 + ((ch ^ (row & 7)) << 4);
            size_t gi = ((size_t)(T - 1) * B + (size_t)blk * MT + row) * 8 + ch;
            g_h0[gi] = *(uint4*)(sm + rdH + sa);
        }
    }
}

// =====================================================================
// Kernel 1: h0 -> LSTM -> LayerNorm(h_T) -> out
// =====================================================================
__global__ void __launch_bounds__(THREADS, 1) k_layer1(
    const float* __restrict__ Wih, const float* __restrict__ Whh,
    const float* __restrict__ bih, const float* __restrict__ bhh,
    const float* __restrict__ gamma, const float* __restrict__ beta,
    float* __restrict__ out)
{
    extern __shared__ __align__(1024) char sm[];
    const uint32_t sb = smem_u32(sm);
    const int tid = threadIdx.x, wid = tid >> 5, lane = tid & 31;
    const int mrow0 = (wid & 1) * 64;
    const int ncol0 = (wid >> 1) * 32;
    const int blk = blockIdx.x;

    // prefetch h0_0 early (overlaps weight staging)
    uint4 ph[2];
    {
        size_t base = ((size_t)0 * B + (size_t)blk * MT) * 8;
#pragma unroll
        for (int r = 0; r < 2; r++) ph[r] = g_h0[base + tid + r * THREADS];
    }

    // zero h1 ping-pong
    for (int i = tid; i < 32768 / 16; i += THREADS)
        ((uint4*)(sm + SM1_H1H0))[i] = make_uint4(0, 0, 0, 0);
    // weights fp16 (swizzled) + bias table (reordered)
    for (int idx = tid; idx < 256 * 64; idx += THREADS) {
        int g = idx >> 6, k = idx & 63;
        int n = (g & 63) * 4 + (g >> 6);
        int ba = n * 128 + (((k >> 3) ^ (n & 7)) << 4) + ((2 * k) & 15);
        *(__half*)(sm + SM1_WIH + ba) = __float2half_rn(Wih[idx]);
        *(__half*)(sm + SM1_WHH + ba) = __float2half_rn(Whh[idx]);
    }
    for (int g = tid; g < 256; g += THREADS) {
        int n = (g & 63) * 4 + (g >> 6);
        ((float*)(sm + SM1_BIAS))[n] = bih[g] + bhh[g];
    }
    // stage h0_0 into X0
#pragma unroll
    for (int r = 0; r < 2; r++) {
        int i = tid + r * THREADS;
        int row = i >> 3, ch = i & 7;
        uint32_t sa = row * 128 + ((ch ^ (row & 7)) << 4);
        *(uint4*)(sm + SM1_X0 + sa) = ph[r];
    }
    __syncthreads();

    float cs[4][4];
#pragma unroll
    for (int a = 0; a < 4; a++)
#pragma unroll
        for (int b = 0; b < 4; b++) cs[a][b] = 0.f;

    for (int t = 0; t < T; t++) {
        const int rdH = (t & 1) ? SM1_H1H1 : SM1_H1H0;
        const int wrH = (t & 1) ? SM1_H1H0 : SM1_H1H1;
        const int rdX = (t & 1) ? SM1_X1 : SM1_X0;
        const int wrX = (t & 1) ? SM1_X0 : SM1_X1;

        // prefetch h0_{t+1} (LDG at top; lands before staging below)
        if (t + 1 < T) {
            size_t base = ((size_t)(t + 1) * B + (size_t)blk * MT) * 8;
#pragma unroll
            for (int r = 0; r < 2; r++) ph[r] = g_h0[base + tid + r * THREADS];
        }

        float acc[4][4][4];
#pragma unroll
        for (int a = 0; a < 4; a++)
#pragma unroll
            for (int b = 0; b < 4; b++)
#pragma unroll
                for (int q = 0; q < 4; q++) acc[a][b][q] = 0.f;

        gemm_acc<4, 128, 128, true, true, 4>(sb + rdH, sb + SM1_WHH,
                                             acc, mrow0, ncol0, lane);
        gemm_acc<4, 128, 128, true, true, 4>(sb + rdX, sb + SM1_WIH,
                                             acc, mrow0, ncol0, lane);

        // stage h0_{t+1} into pong (disjoint from rdX) — no barrier needed
        if (t + 1 < T) {
#pragma unroll
            for (int r = 0; r < 2; r++) {
                int i = tid + r * THREADS;
                int row = i >> 3, ch = i & 7;
                uint32_t sa = row * 128 + ((ch ^ (row & 7)) << 4);
                *(uint4*)(sm + wrX + sa) = ph[r];
            }
        }

        if (t < T - 1) {
            epilogue<false, 4>(acc, cs, sm, wrH,
                               (const float*)(sm + SM1_BIAS), 0,
                               mrow0, ncol0, lane);
        } else {
            // last step: write fp32 h into LN buffer (full precision for LayerNorm)
            epilogue<true, 4>(acc, cs, sm, 0,
                              (const float*)(sm + SM1_BIAS), SM1_LN,
                              mrow0, ncol0, lane);
        }
        __syncthreads();   // single barrier per timestep
    }

    // LayerNorm over final h1 (fp32 buffer), one thread per sample
    if (tid < MT) {
        const float* row = (const float*)(sm + SM1_LN) + tid * 68;
        float s = 0.f;
#pragma unroll
        for (int k = 0; k < 64; k++) s += row[k];
        float mean = s * (1.f / 64.f);
        float vs = 0.f;
#pragma unroll
        for (int k = 0; k < 64; k++) { float d = row[k] - mean; vs += d * d; }
        float rstd = rsqrtf(vs * (1.f / 64.f) + 1e-5f);
        float4* op = (float4*)(out + (size_t)(blk * MT + tid) * 64);
#pragma unroll
        for (int k = 0; k < 64; k += 4) {
            float4 o;
            o.x = (row[k + 0] - mean) * rstd * gamma[k + 0] + beta[k + 0];
            o.y = (row[k + 1] - mean) * rstd * gamma[k + 1] + beta[k + 1];
            o.z = (row[k + 2] - mean) * rstd * gamma[k + 2] + beta[k + 2];
            o.w = (row[k + 3] - mean) * rstd * gamma[k + 3] + beta[k + 3];
            op[k >> 2] = o;
        }
    }
}

// =====================================================================
extern "C" void kernel_launch(void* const* d_in, const int* in_sizes, int n_in,
                              void* d_out, int out_size) {
    (void)in_sizes; (void)n_in; (void)out_size;
    const float* x     = (const float*)d_in[0];
    const float* Wih0  = (const float*)d_in[1];
    const float* Whh0  = (const float*)d_in[2];
    const float* bih0  = (const float*)d_in[3];
    const float* bhh0  = (const float*)d_in[4];
    const float* Wih1  = (const float*)d_in[5];
    const float* Whh1  = (const float*)d_in[6];
    const float* bih1  = (const float*)d_in[7];
    const float* bhh1  = (const float*)d_in[8];
    const float* gamma = (const float*)d_in[9];
    const float* beta  = (const float*)d_in[10];
    float* out = (float*)d_out;

    cudaFuncSetAttribute(k_layer0, cudaFuncAttributeMaxDynamicSharedMemorySize, SM0_TOTAL);
    cudaFuncSetAttribute(k_layer1, cudaFuncAttributeMaxDynamicSharedMemorySize, SM1_TOTAL);

    k_layer0<<<B / MT, THREADS, SM0_TOTAL>>>(x, Wih0, Whh0, bih0, bhh0);
    k_layer1<<<B / MT, THREADS, SM1_TOTAL>>>(Wih1, Whh1, bih1, bhh1, gamma, beta, out);
}

// round 17
// speedup vs baseline: 1.3744x; 1.1773x over previous
#include <cuda_runtime.h>
#include <cuda_fp16.h>
#include <cstdint>
#include <cstddef>

constexpr int B  = 65536;
constexpr int T  = 30;
constexpr int MT = 128;          // samples per CTA
constexpr int THREADS = 512;     // 16 warps: 2 (m) x 8 (n), warp tile 64x32

// ---------------- Kernel0 smem offsets (bytes) ----------------
constexpr int SM0_X0    = 0;       // x ping [128][48B] K=16 (cols0-8, rest 0)
constexpr int SM0_X1    = 6144;    // x pong
constexpr int SM0_WIH   = 12288;   // [256 n][48B] Wih fp16 (cols0-8, rest 0)
constexpr int SM0_BIAS  = 24576;   // 256 f32, reordered gate cols
constexpr int SM0_HH0   = 25600;   // h0 fp16 ping [128][128B] swz
constexpr int SM0_HH1   = 41984;   // h0 fp16 pong
constexpr int SM0_WHH   = 58368;   // [256][128B] swz
constexpr int SM0_TOTAL = 91136;

// ---------------- Kernel1 smem offsets ----------------
constexpr int SM1_X0    = 0;       // staged h0 ping [128][128B] swz
constexpr int SM1_X1    = 16384;   // staged h0 pong
constexpr int SM1_H1H0  = 32768;   // h1 fp16 ping
constexpr int SM1_H1H1  = 49152;   // h1 fp16 pong
constexpr int SM1_WIH   = 65536;   // [256][128B] swz
constexpr int SM1_WHH   = 98304;
constexpr int SM1_BIAS  = 131072;  // 256 f32, reordered gate cols
constexpr int SM1_LN    = 132096;  // [128][68] f32 final h for LayerNorm
constexpr int SM1_TOTAL = 132096 + 128 * 68 * 4;   // 166912

// scratch: layer0 h fp16, [t][sample][8 x 16B chunks], coalesced both ways
__device__ uint4 g_h0[(size_t)T * B * 8];

// ---------------- helpers ----------------
__device__ __forceinline__ uint32_t smem_u32(const void* p) {
    uint32_t a;
    asm("{ .reg .u64 t; cvta.to.shared.u64 t, %1; cvt.u32.u64 %0, t; }"
        : "=r"(a) : "l"(p));
    return a;
}
// hardware tanh (sm_75+): 1 MUFU op
__device__ __forceinline__ float tanha(float x) {
    float r;
    asm("tanh.approx.f32 %0, %1;" : "=f"(r) : "f"(x));
    return r;
}
// packed fp16x2 hardware tanh: 1 MUFU op for two values
__device__ __forceinline__ uint32_t tanh2(uint32_t x2) {
    uint32_t r;
    asm("tanh.approx.f16x2 %0, %1;" : "=r"(r) : "r"(x2));
    return r;
}
__device__ __forceinline__ uint32_t f2h2(float a, float b) {
    __half2 h = __floats2half2_rn(a, b);
    return *reinterpret_cast<uint32_t*>(&h);
}
__device__ __forceinline__ float2 h22f2(uint32_t p) {
    return __half22float2(*reinterpret_cast<__half2*>(&p));
}
__device__ __forceinline__ uint32_t hfma2(uint32_t a, uint32_t b, uint32_t c) {
    uint32_t d;
    asm("fma.rn.f16x2 %0, %1, %2, %3;" : "=r"(d) : "r"(a), "r"(b), "r"(c));
    return d;
}

__device__ __forceinline__ void ldsm4(uint32_t (&r)[4], uint32_t addr) {
    asm volatile("ldmatrix.sync.aligned.m8n8.x4.shared.b16 {%0,%1,%2,%3}, [%4];"
        : "=r"(r[0]), "=r"(r[1]), "=r"(r[2]), "=r"(r[3]) : "r"(addr));
}
__device__ __forceinline__ void mma_f16(float (&d)[4], const uint32_t (&a)[4],
                                        uint32_t b0, uint32_t b1) {
    asm volatile(
        "mma.sync.aligned.m16n8k16.row.col.f32.f16.f16.f32 "
        "{%0,%1,%2,%3},{%4,%5,%6,%7},{%8,%9},{%0,%1,%2,%3};"
        : "+f"(d[0]), "+f"(d[1]), "+f"(d[2]), "+f"(d[3])
        : "r"(a[0]), "r"(a[1]), "r"(a[2]), "r"(a[3]), "r"(b0), "r"(b1));
}
// zero-init variant: c operand = zero quad (acc needs no pre-zeroing)
__device__ __forceinline__ void mma_f16_z(float (&d)[4], const uint32_t (&a)[4],
                                          uint32_t b0, uint32_t b1,
                                          const float (&z)[4]) {
    asm volatile(
        "mma.sync.aligned.m16n8k16.row.col.f32.f16.f16.f32 "
        "{%0,%1,%2,%3},{%4,%5,%6,%7},{%8,%9},{%10,%11,%12,%13};"
        : "=f"(d[0]), "=f"(d[1]), "=f"(d[2]), "=f"(d[3])
        : "r"(a[0]), "r"(a[1]), "r"(a[2]), "r"(a[3]), "r"(b0), "r"(b1),
          "f"(z[0]), "f"(z[1]), "f"(z[2]), "f"(z[3]));
}

// Warp GEMM: A tile (MI*16 rows) x one B tile (32 n-cols), acc[MI][4][4].
// KS k16-steps; strides in bytes; SW = XOR-16B-chunk swizzle for 128B-stride tiles.
// ZI: kk==0 writes acc via zero c-operand (no acc pre-zeroing required).
template<int KS, int SA, int SB, bool SWA, bool SWB, int MI, bool ZI>
__device__ __forceinline__ void gemm_acc(uint32_t aBase, uint32_t bBase,
                                         float (&acc)[MI][4][4],
                                         const float (&zq)[4],
                                         int mrow0, int ncol0, int lane)
{
    const int grp = lane >> 3, j = lane & 7;
    const int arow_off = ((grp & 1) << 3) + j;
    const int ach_off  = grp >> 1;
    const int brow_off = ((grp >> 1) << 3) + j;
    const int bch_off  = grp & 1;
#pragma unroll
    for (int kk = 0; kk < KS; kk++) {
        uint32_t a[MI][4];
#pragma unroll
        for (int mi = 0; mi < MI; mi++) {
            int row = mrow0 + mi * 16 + arow_off;
            int ch  = 2 * kk + ach_off;
            uint32_t ad = aBase + row * SA + ((SWA ? (ch ^ (row & 7)) : ch) << 4);
            ldsm4(a[mi], ad);
        }
#pragma unroll
        for (int ni = 0; ni < 2; ni++) {
            int row = ncol0 + ni * 16 + brow_off;
            int ch  = 2 * kk + bch_off;
            uint32_t bd = bBase + row * SB + ((SWB ? (ch ^ (row & 7)) : ch) << 4);
            uint32_t bf[4];
            ldsm4(bf, bd);
#pragma unroll
            for (int mi = 0; mi < MI; mi++) {
                if (ZI && kk == 0) {
                    mma_f16_z(acc[mi][2 * ni],     a[mi], bf[0], bf[1], zq);
                    mma_f16_z(acc[mi][2 * ni + 1], a[mi], bf[2], bf[3], zq);
                } else {
                    mma_f16(acc[mi][2 * ni],     a[mi], bf[0], bf[1]);
                    mma_f16(acc[mi][2 * ni + 1], a[mi], bf[2], bf[3]);
                }
            }
        }
    }
}

// Gate epilogue, full half2 gate path:
//   even lanes hold (i,f) cols: both sigmoid -> prescale (0.5,0.5)
//   odd  lanes hold (g,o) cols: (tanh, sigmoid) -> prescale (1.0,0.5)
// biasS[nj] = packed fp16 (b0*s0, b1*0.5), preloaded outside t-loop.
// One HFMA2 folds bias+prescale; tanh2 per pair; raw pair exchanged via one
// half2 shfl; sigmoid post-affine applied after unpack. Cell math stays fp32.
template<bool LNOUT, int MI>
__device__ __forceinline__ void epilogue(float (&acc)[MI][4][4], float (&cs)[MI][4],
                                         char* sm, int hhOff,
                                         const uint32_t (&biasS)[4], uint32_t sconst,
                                         int lnOff, int mrow0, int ncol0, int lane)
{
    const int odd = lane & 1;
    const int rb  = mrow0 + (lane >> 2) + (odd ? 8 : 0);
    const int ub  = (ncol0 >> 2) + ((lane & 3) >> 1);
#pragma unroll
    for (int mi = 0; mi < MI; mi++) {
#pragma unroll
        for (int nj = 0; nj < 4; nj++) {
            // pack preactivations, fused prescale+bias, packed tanh
            uint32_t p01 = hfma2(f2h2(acc[mi][nj][0], acc[mi][nj][1]),
                                 sconst, biasS[nj]);
            uint32_t p23 = hfma2(f2h2(acc[mi][nj][2], acc[mi][nj][3]),
                                 sconst, biasS[nj]);
            uint32_t t01 = tanh2(p01);
            uint32_t t23 = tanh2(p23);
            // exchange raw packed pair: even sends row r+8 (i,f), odd sends row r (g,o)
            uint32_t pv = odd ? t01 : t23;
            uint32_t pr = __shfl_xor_sync(0xffffffffu, pv, 1);
            uint32_t pif = odd ? pr : t01;   // (t_i, t_f), sigmoid-prescaled
            uint32_t pgo = odd ? t23 : pr;   // (t_g full-scale, t_o prescaled)
            float2 fif = h22f2(pif);
            float2 fgo = h22f2(pgo);
            float iv = fmaf(fif.x, 0.5f, 0.5f);
            float fv = fmaf(fif.y, 0.5f, 0.5f);
            float gv = fgo.x;
            float ov = fmaf(fgo.y, 0.5f, 0.5f);
            float cc = fmaf(fv, cs[mi][nj], iv * gv);
            cs[mi][nj] = cc;
            float hv = ov * tanha(cc);
            int row = rb + mi * 16;
            int u   = ub + 2 * nj;
            if (LNOUT) {
                ((float*)(sm + lnOff))[row * 68 + u] = hv;
            } else {
                __half hh = __float2half_rn(hv);
                int ch = u >> 3;
                int ba = row * 128 + ((ch ^ (row & 7)) << 4) + ((2 * u) & 15);
                *(__half*)(sm + hhOff + ba) = hh;
            }
        }
    }
}

// =====================================================================
// Kernel 0: x -> h0 (fp16) -> global scratch
// =====================================================================
__global__ void __launch_bounds__(THREADS, 1) k_layer0(
    const float* __restrict__ x,
    const float* __restrict__ Wih, const float* __restrict__ Whh,
    const float* __restrict__ bih, const float* __restrict__ bhh)
{
    extern __shared__ __align__(1024) char sm[];
    const uint32_t sb = smem_u32(sm);
    const int tid = threadIdx.x, wid = tid >> 5, lane = tid & 31;
    const int mrow0 = (wid & 1) * 64;
    const int ncol0 = (wid >> 1) * 32;
    const int blk = blockIdx.x;

    // prefetch x_0 early (overlaps weight staging)
    float xv[9];
    if (tid < MT) {
        const float* xr = x + ((size_t)(blk * MT + tid) * T + 0) * 9;
#pragma unroll
        for (int i = 0; i < 9; i++) xv[i] = xr[i];
    }

    // zero h ping-pong + X/WIH regions
    for (int i = tid; i < 32768 / 16; i += THREADS)
        ((uint4*)(sm + SM0_HH0))[i] = make_uint4(0, 0, 0, 0);
    for (int i = tid; i < 24576 / 16; i += THREADS)
        ((uint4*)(sm + SM0_X0))[i] = make_uint4(0, 0, 0, 0);
    __syncthreads();

    // Wih0 fp16 [256 n][48B]: cols 0-8 weights, rest zero; bias fp32 table
    for (int idx = tid; idx < 256 * 9; idx += THREADS) {
        int g = idx / 9, i2 = idx - g * 9;
        int n = (g & 63) * 4 + (g >> 6);
        *(__half*)(sm + SM0_WIH + n * 48 + 2 * i2) = __float2half_rn(Wih[idx]);
    }
    for (int g = tid; g < 256; g += THREADS) {
        int n = (g & 63) * 4 + (g >> 6);
        ((float*)(sm + SM0_BIAS))[n] = bih[g] + bhh[g];
    }
    // Whh0 fp16 tile (swizzled)
    for (int idx = tid; idx < 256 * 64; idx += THREADS) {
        int g = idx >> 6, k = idx & 63;
        int n = (g & 63) * 4 + (g >> 6);
        int ba = n * 128 + (((k >> 3) ^ (n & 7)) << 4) + ((2 * k) & 15);
        *(__half*)(sm + SM0_WHH + ba) = __float2half_rn(Whh[idx]);
    }
    // stage x_0 into X0
    if (tid < MT) {
        char* rp = sm + SM0_X0 + tid * 48;
        ((uint4*)rp)[0] = make_uint4(f2h2(xv[0], xv[1]), f2h2(xv[2], xv[3]),
                                     f2h2(xv[4], xv[5]), f2h2(xv[6], xv[7]));
        ((uint4*)rp)[1] = make_uint4(f2h2(xv[8], 0.f), 0, 0, 0);
    }
    __syncthreads();

    // preload pre-scaled fp16 bias pairs + prescale const (loop-invariant)
    uint32_t biasS[4], sconst;
    {
        const float* bt = (const float*)(sm + SM0_BIAS);
        const float se0 = (lane & 1) ? 1.0f : 0.5f;
        sconst = f2h2(se0, 0.5f);
#pragma unroll
        for (int nj = 0; nj < 4; nj++) {
            int n0 = ncol0 + nj * 8 + 2 * (lane & 3);
            biasS[nj] = f2h2(bt[n0] * se0, bt[n0 + 1] * 0.5f);
        }
    }

    const float zq[4] = {0.f, 0.f, 0.f, 0.f};
    float cs[4][4];
#pragma unroll
    for (int a = 0; a < 4; a++)
#pragma unroll
        for (int b = 0; b < 4; b++) cs[a][b] = 0.f;

    for (int t = 0; t < T; t++) {
        const int rdH = (t & 1) ? SM0_HH1 : SM0_HH0;
        const int wrH = (t & 1) ? SM0_HH0 : SM0_HH1;
        const int rdX = (t & 1) ? SM0_X1 : SM0_X0;
        const int wrX = (t & 1) ? SM0_X0 : SM0_X1;

        // prefetch x_{t+1} (LDG issued at top; lands before staging below)
        if (t + 1 < T && tid < MT) {
            const float* xr = x + ((size_t)(blk * MT + tid) * T + (t + 1)) * 9;
#pragma unroll
            for (int i = 0; i < 9; i++) xv[i] = xr[i];
        }

        // store h_{t-1} -> global scratch (reads rdH: read/read vs H-GEMM)
        if (t > 0) {
            for (int i = tid; i < 1024; i += THREADS) {
                int row = i >> 3, ch = i & 7;
                uint32_t sa = row * 128 + ((ch ^ (row & 7)) << 4);
                size_t gi = ((size_t)(t - 1) * B + (size_t)blk * MT + row) * 8 + ch;
                g_h0[gi] = *(uint4*)(sm + rdH + sa);
            }
        }

        float acc[4][4][4];   // first GEMM zero-inits via MMA c-operand
        gemm_acc<4, 128, 128, true, true, 4, true>(sb + rdH, sb + SM0_WHH,
                                                   acc, zq, mrow0, ncol0, lane);
        gemm_acc<1, 48, 48, false, false, 4, false>(sb + rdX, sb + SM0_WIH,
                                                    acc, zq, mrow0, ncol0, lane);

        // stage x_{t+1} into pong (disjoint from rdX) — no barrier needed
        if (t + 1 < T && tid < MT) {
            char* rp = sm + wrX + tid * 48;
            ((uint4*)rp)[0] = make_uint4(f2h2(xv[0], xv[1]), f2h2(xv[2], xv[3]),
                                         f2h2(xv[4], xv[5]), f2h2(xv[6], xv[7]));
            ((uint4*)rp)[1] = make_uint4(f2h2(xv[8], 0.f), 0, 0, 0);
        }

        // epilogue writes wrH (disjoint from rdH/rdX) — no barrier before it
        epilogue<false, 4>(acc, cs, sm, wrH, biasS, sconst,
                           0, mrow0, ncol0, lane);
        __syncthreads();   // single barrier per timestep
    }

    // store final h_{T-1} (lives in buf[T&1] = buf0)
    {
        const int rdH = (T & 1) ? SM0_HH1 : SM0_HH0;
        for (int i = tid; i < 1024; i += THREADS) {
            int row = i >> 3, ch = i & 7;
            uint32_t sa = row * 128 + ((ch ^ (row & 7)) << 4);
            size_t gi = ((size_t)(T - 1) * B + (size_t)blk * MT + row) * 8 + ch;
            g_h0[gi] = *(uint4*)(sm + rdH + sa);
        }
    }
}

// =====================================================================
// Kernel 1: h0 -> LSTM -> LayerNorm(h_T) -> out
// =====================================================================
__global__ void __launch_bounds__(THREADS, 1) k_layer1(
    const float* __restrict__ Wih, const float* __restrict__ Whh,
    const float* __restrict__ bih, const float* __restrict__ bhh,
    const float* __restrict__ gamma, const float* __restrict__ beta,
    float* __restrict__ out)
{
    extern __shared__ __align__(1024) char sm[];
    const uint32_t sb = smem_u32(sm);
    const int tid = threadIdx.x, wid = tid >> 5, lane = tid & 31;
    const int mrow0 = (wid & 1) * 64;
    const int ncol0 = (wid >> 1) * 32;
    const int blk = blockIdx.x;

    // prefetch h0_0 early (overlaps weight staging)
    uint4 ph[2];
    {
        size_t base = ((size_t)0 * B + (size_t)blk * MT) * 8;
#pragma unroll
        for (int r = 0; r < 2; r++) ph[r] = g_h0[base + tid + r * THREADS];
    }

    // zero h1 ping-pong
    for (int i = tid; i < 32768 / 16; i += THREADS)
        ((uint4*)(sm + SM1_H1H0))[i] = make_uint4(0, 0, 0, 0);
    // weights fp16 (swizzled) + bias table (reordered)
    for (int idx = tid; idx < 256 * 64; idx += THREADS) {
        int g = idx >> 6, k = idx & 63;
        int n = (g & 63) * 4 + (g >> 6);
        int ba = n * 128 + (((k >> 3) ^ (n & 7)) << 4) + ((2 * k) & 15);
        *(__half*)(sm + SM1_WIH + ba) = __float2half_rn(Wih[idx]);
        *(__half*)(sm + SM1_WHH + ba) = __float2half_rn(Whh[idx]);
    }
    for (int g = tid; g < 256; g += THREADS) {
        int n = (g & 63) * 4 + (g >> 6);
        ((float*)(sm + SM1_BIAS))[n] = bih[g] + bhh[g];
    }
    // stage h0_0 into X0
#pragma unroll
    for (int r = 0; r < 2; r++) {
        int i = tid + r * THREADS;
        int row = i >> 3, ch = i & 7;
        uint32_t sa = row * 128 + ((ch ^ (row & 7)) << 4);
        *(uint4*)(sm + SM1_X0 + sa) = ph[r];
    }
    __syncthreads();

    // preload pre-scaled fp16 bias pairs + prescale const (loop-invariant)
    uint32_t biasS[4], sconst;
    {
        const float* bt = (const float*)(sm + SM1_BIAS);
        const float se0 = (lane & 1) ? 1.0f : 0.5f;
        sconst = f2h2(se0, 0.5f);
#pragma unroll
        for (int nj = 0; nj < 4; nj++) {
            int n0 = ncol0 + nj * 8 + 2 * (lane & 3);
            biasS[nj] = f2h2(bt[n0] * se0, bt[n0 + 1] * 0.5f);
        }
    }

    const float zq[4] = {0.f, 0.f, 0.f, 0.f};
    float cs[4][4];
#pragma unroll
    for (int a = 0; a < 4; a++)
#pragma unroll
        for (int b = 0; b < 4; b++) cs[a][b] = 0.f;

    for (int t = 0; t < T; t++) {
        const int rdH = (t & 1) ? SM1_H1H1 : SM1_H1H0;
        const int wrH = (t & 1) ? SM1_H1H0 : SM1_H1H1;
        const int rdX = (t & 1) ? SM1_X1 : SM1_X0;
        const int wrX = (t & 1) ? SM1_X0 : SM1_X1;

        // prefetch h0_{t+1} (LDG at top; lands before staging below)
        if (t + 1 < T) {
            size_t base = ((size_t)(t + 1) * B + (size_t)blk * MT) * 8;
#pragma unroll
            for (int r = 0; r < 2; r++) ph[r] = g_h0[base + tid + r * THREADS];
        }

        float acc[4][4][4];   // first GEMM zero-inits via MMA c-operand
        gemm_acc<4, 128, 128, true, true, 4, true>(sb + rdH, sb + SM1_WHH,
                                                   acc, zq, mrow0, ncol0, lane);
        gemm_acc<4, 128, 128, true, true, 4, false>(sb + rdX, sb + SM1_WIH,
                                                    acc, zq, mrow0, ncol0, lane);

        // stage h0_{t+1} into pong (disjoint from rdX) — no barrier needed
        if (t + 1 < T) {
#pragma unroll
            for (int r = 0; r < 2; r++) {
                int i = tid + r * THREADS;
                int row = i >> 3, ch = i & 7;
                uint32_t sa = row * 128 + ((ch ^ (row & 7)) << 4);
                *(uint4*)(sm + wrX + sa) = ph[r];
            }
        }

        if (t < T - 1) {
            epilogue<false, 4>(acc, cs, sm, wrH, biasS, sconst,
                               0, mrow0, ncol0, lane);
        } else {
            // last step: write fp32 h into LN buffer (full precision for LayerNorm)
            epilogue<true, 4>(acc, cs, sm, 0, biasS, sconst,
                              SM1_LN, mrow0, ncol0, lane);
        }
        __syncthreads();   // single barrier per timestep
    }

    // LayerNorm over final h1 (fp32 buffer), one thread per sample
    if (tid < MT) {
        const float* row = (const float*)(sm + SM1_LN) + tid * 68;
        float s = 0.f;
#pragma unroll
        for (int k = 0; k < 64; k++) s += row[k];
        float mean = s * (1.f / 64.f);
        float vs = 0.f;
#pragma unroll
        for (int k = 0; k < 64; k++) { float d = row[k] - mean; vs += d * d; }
        float rstd = rsqrtf(vs * (1.f / 64.f) + 1e-5f);
        float4* op = (float4*)(out + (size_t)(blk * MT + tid) * 64);
#pragma unroll
        for (int k = 0; k < 64; k += 4) {
            float4 o;
            o.x = (row[k + 0] - mean) * rstd * gamma[k + 0] + beta[k + 0];
            o.y = (row[k + 1] - mean) * rstd * gamma[k + 1] + beta[k + 1];
            o.z = (row[k + 2] - mean) * rstd * gamma[k + 2] + beta[k + 2];
            o.w = (row[k + 3] - mean) * rstd * gamma[k + 3] + beta[k + 3];
            op[k >> 2] = o;
        }
    }
}

// =====================================================================
extern "C" void kernel_launch(void* const* d_in, const int* in_sizes, int n_in,
                              void* d_out, int out_size) {
    (void)in_sizes; (void)n_in; (void)out_size;
    const float* x     = (const float*)d_in[0];
    const float* Wih0  = (const float*)d_in[1];
    const float* Whh0  = (const float*)d_in[2];
    const float* bih0  = (const float*)d_in[3];
    const float* bhh0  = (const float*)d_in[4];
    const float* Wih1  = (const float*)d_in[5];
    const float* Whh1  = (const float*)d_in[6];
    const float* bih1  = (const float*)d_in[7];
    const float* bhh1  = (const float*)d_in[8];
    const float* gamma = (const float*)d_in[9];
    const float* beta  = (const float*)d_in[10];
    float* out = (float*)d_out;

    cudaFuncSetAttribute(k_layer0, cudaFuncAttributeMaxDynamicSharedMemorySize, SM0_TOTAL);
    cudaFuncSetAttribute(k_layer1, cudaFuncAttributeMaxDynamicSharedMemorySize, SM1_TOTAL);

    k_layer0<<<B / MT, THREADS, SM0_TOTAL>>>(x, Wih0, Whh0, bih0, bhh0);
    k_layer1<<<B / MT, THREADS, SM1_TOTAL>>>(Wih1, Whh1, bih1, bhh1, gamma, beta, out);
}